// round 15
// baseline (speedup 1.0000x reference)
#include <cuda_runtime.h>
#include <cuda_bf16.h>
#include <stdint.h>

#define NB 4
#define CH 128
#define LL 4096
#define SCALE_L2E ((float)(0.08838834764831845 * 1.4426950408889634))

// ---------------------------------------------------------------------------
// Scratch (allocation-free: static device globals)
// ---------------------------------------------------------------------------
__device__ __nv_bfloat16  g_qT[(size_t)NB * LL * CH];  // q^T [n][m][c]
__device__ __nv_bfloat16  g_kT[(size_t)NB * LL * CH];  // k^T [n][l][c], pre-scaled by SCALE*log2e
__device__ __nv_bfloat16  g_vB[(size_t)NB * CH * LL];  // v   [n][c][l]
__device__ __nv_bfloat16  g_s[(size_t)NB * LL * LL];   // raw scores S [n][l][m] bf16 (134MB)
__device__ float          g_mpA[NB * LL];              // raw sum exp2 for m-half 0
__device__ float          g_mpB[NB * LL];              // raw sum exp2 for m-half 1
__device__ float          g_mp [NB * LL];              // merged log2(sum)
__device__ float          g_part[2 * (size_t)NB * CH * LL]; // attn partials per l-half
__device__ int            g_sem[NB * 32];              // combine semaphores (zero-init)

// ---------------------------------------------------------------------------
// Helpers
// ---------------------------------------------------------------------------
__device__ __forceinline__ uint32_t smem_u32(const void* p) {
    uint32_t a;
    asm("{ .reg .u64 t; cvta.to.shared.u64 t, %1; cvt.u32.u64 %0, t; }"
        : "=r"(a) : "l"(p));
    return a;
}
__device__ __forceinline__ uint32_t pk_bf16(float a, float b) {
    __nv_bfloat162 t = __floats2bfloat162_rn(a, b);
    return *reinterpret_cast<uint32_t*>(&t);
}
__device__ __forceinline__ float fexp2(float x) {
    float y; asm("ex2.approx.f32 %0, %1;" : "=f"(y) : "f"(x)); return y;
}
__device__ __forceinline__ float flog2(float x) {
    float y; asm("lg2.approx.f32 %0, %1;" : "=f"(y) : "f"(x)); return y;
}

__device__ __forceinline__ uint32_t swz(int row, int ch, int pitch) {
    return (uint32_t)row * (uint32_t)pitch + (uint32_t)((ch ^ (row & 7)) << 4);
}
__device__ __forceinline__ void ldsm_x4(uint32_t addr, uint32_t* r) {
    asm volatile("ldmatrix.sync.aligned.m8n8.x4.shared.b16 {%0,%1,%2,%3}, [%4];"
        : "=r"(r[0]), "=r"(r[1]), "=r"(r[2]), "=r"(r[3]) : "r"(addr));
}
__device__ __forceinline__ void ldsm_x4_trans(uint32_t addr, uint32_t* r) {
    asm volatile("ldmatrix.sync.aligned.m8n8.x4.trans.shared.b16 {%0,%1,%2,%3}, [%4];"
        : "=r"(r[0]), "=r"(r[1]), "=r"(r[2]), "=r"(r[3]) : "r"(addr));
}
__device__ __forceinline__ uint32_t a_addr(uint32_t tb, int r0, int kk, int lane, int pitch) {
    return tb + swz(r0 + (lane & 15), kk * 2 + (lane >> 4), pitch);
}
__device__ __forceinline__ uint32_t b_addr(uint32_t tb, int n0, int kk, int lane, int pitch) {
    int g = lane >> 3;
    return tb + swz(n0 + (lane & 7) + ((g & 2) ? 8 : 0), kk * 2 + (g & 1), pitch);
}
// trans B-fragment address: tile stored [l][m] pitch 256; n0 = m base, kk = 16-l block.
__device__ __forceinline__ uint32_t bt_addr(uint32_t tb, int n0, int kk, int lane) {
    int row  = kk * 16 + (lane & 7) + ((lane & 8) ? 8 : 0);
    int colm = n0 + ((lane & 16) ? 8 : 0);
    return tb + swz(row, colm >> 3, 256);
}
__device__ __forceinline__ void mma_bf16(float* d, const uint32_t* a, const uint32_t* b) {
    asm volatile(
        "mma.sync.aligned.m16n8k16.row.col.f32.bf16.bf16.f32 "
        "{%0,%1,%2,%3}, {%4,%5,%6,%7}, {%8,%9}, {%0,%1,%2,%3};"
        : "+f"(d[0]), "+f"(d[1]), "+f"(d[2]), "+f"(d[3])
        : "r"(a[0]), "r"(a[1]), "r"(a[2]), "r"(a[3]), "r"(b[0]), "r"(b[1]));
}
__device__ __forceinline__ void cpa16(uint32_t dst, const void* src) {
    asm volatile("cp.async.cg.shared.global [%0], [%1], 16;" :: "r"(dst), "l"(src));
}
#define CPA_COMMIT() asm volatile("cp.async.commit_group;" ::: "memory")
#define CPA_WAIT(n)  asm volatile("cp.async.wait_group %0;" :: "n"(n) : "memory")

// ---------------------------------------------------------------------------
// Kernel A: q/k/v via HMMA with in-kernel x transpose.
// grid (64,4), 128 thr. smem: xt 16K | ts/wt 33.3K (aliased) | bias 512
// ---------------------------------------------------------------------------
__global__ __launch_bounds__(128) void qkv_kernel(
    const float* __restrict__ x,
    const float* __restrict__ Wq, const float* __restrict__ bq,
    const float* __restrict__ Wk, const float* __restrict__ bk,
    const float* __restrict__ Wv, const float* __restrict__ bv)
{
    extern __shared__ char smc[];
    char*  xt   = smc;
    float* ts   = (float*)(smc + 16384);
    char*  wt   = smc + 16384;
    float* bias = (float*)(smc + 49664);
    uint32_t xtb = smem_u32(xt), wtb = smem_u32(wt);
    int n = blockIdx.y, m0 = blockIdx.x * 64, t = threadIdx.x;
    int lane = t & 31, w = t >> 5;

    const float* xb = x + ((size_t)n * CH + t) * LL + m0;
#pragma unroll
    for (int k = 0; k < 16; k++) {
        float4 f = *(const float4*)(xb + k * 4);
        ts[t * 65 + k * 4 + 0] = f.x;
        ts[t * 65 + k * 4 + 1] = f.y;
        ts[t * 65 + k * 4 + 2] = f.z;
        ts[t * 65 + k * 4 + 3] = f.w;
    }
    __syncthreads();

    {
        int ml = t >> 1, half = t & 1;
#pragma unroll
        for (int u = 0; u < 8; u++) {
            int cb = half * 64 + u * 8;
            uint4 o;
            o.x = pk_bf16(ts[(cb + 0) * 65 + ml], ts[(cb + 1) * 65 + ml]);
            o.y = pk_bf16(ts[(cb + 2) * 65 + ml], ts[(cb + 3) * 65 + ml]);
            o.z = pk_bf16(ts[(cb + 4) * 65 + ml], ts[(cb + 5) * 65 + ml]);
            o.w = pk_bf16(ts[(cb + 6) * 65 + ml], ts[(cb + 7) * 65 + ml]);
            *(uint4*)(xt + swz(ml, half * 8 + u, 256)) = o;
        }
    }

    const float* Wm[3] = {Wq, Wk, Wv};
    const float* Bv[3] = {bq, bk, bv};

    for (int wi = 0; wi < 3; wi++) {
        __syncthreads();
#pragma unroll
        for (int i = t; i < 2048; i += 128) {
            int row = i >> 4, ch = i & 15;
            const float* src = Wm[wi] + row * 128 + ch * 8;
            float4 f0 = *(const float4*)src;
            float4 f1 = *(const float4*)(src + 4);
            uint4 u;
            u.x = pk_bf16(f0.x, f0.y); u.y = pk_bf16(f0.z, f0.w);
            u.z = pk_bf16(f1.x, f1.y); u.w = pk_bf16(f1.z, f1.w);
            *(uint4*)(wt + swz(row, ch, 256)) = u;
        }
        bias[t] = Bv[wi][t];
        __syncthreads();

        if (wi < 2) {
            int lw = w * 16;
            float sacc[16][4];
#pragma unroll
            for (int j = 0; j < 16; j++)
#pragma unroll
                for (int q = 0; q < 4; q++) sacc[j][q] = 0.f;
#pragma unroll
            for (int kk = 0; kk < 8; kk++) {
                uint32_t a[4];
                ldsm_x4(a_addr(xtb, lw, kk, lane, 256), a);
#pragma unroll
                for (int jp = 0; jp < 8; jp++) {
                    uint32_t b[4];
                    ldsm_x4(b_addr(wtb, jp * 16, kk, lane, 256), b);
                    mma_bf16(sacc[jp * 2],     a, b);
                    mma_bf16(sacc[jp * 2 + 1], a, b + 2);
                }
            }
            int mrow = m0 + lw + (lane >> 2);
            __nv_bfloat16* dst = (wi == 0 ? g_qT : g_kT) + (size_t)n * LL * CH;
            float sc = (wi == 0) ? 1.0f : SCALE_L2E;
#pragma unroll
            for (int j = 0; j < 16; j++) {
                int o = (j >> 1) * 16 + (j & 1) * 8 + (lane & 3) * 2;
                float b0 = bias[o], b1 = bias[o + 1];
                *(uint32_t*)(dst + (size_t)mrow * CH + o) =
                    pk_bf16((sacc[j][0] + b0) * sc, (sacc[j][1] + b1) * sc);
                *(uint32_t*)(dst + (size_t)(mrow + 8) * CH + o) =
                    pk_bf16((sacc[j][2] + b0) * sc, (sacc[j][3] + b1) * sc);
            }
        } else {
            int rw2 = w * 32;
            float vacc[16][4];
#pragma unroll
            for (int j = 0; j < 16; j++)
#pragma unroll
                for (int q = 0; q < 4; q++) vacc[j][q] = 0.f;
#pragma unroll
            for (int kk = 0; kk < 8; kk++) {
                uint32_t a0[4], a1[4];
                ldsm_x4(a_addr(wtb, rw2,      kk, lane, 256), a0);
                ldsm_x4(a_addr(wtb, rw2 + 16, kk, lane, 256), a1);
#pragma unroll
                for (int bp = 0; bp < 4; bp++) {
                    uint32_t b[4];
                    ldsm_x4(b_addr(xtb, bp * 16, kk, lane, 256), b);
                    mma_bf16(vacc[bp * 2],         a0, b);
                    mma_bf16(vacc[bp * 2 + 1],     a0, b + 2);
                    mma_bf16(vacc[8 + bp * 2],     a1, b);
                    mma_bf16(vacc[8 + bp * 2 + 1], a1, b + 2);
                }
            }
#pragma unroll
            for (int set = 0; set < 2; set++) {
                int o = rw2 + set * 16 + (lane >> 2);
                float bo0 = bias[o], bo1 = bias[o + 8];
#pragma unroll
                for (int j = 0; j < 8; j++) {
                    int mc = m0 + j * 8 + (lane & 3) * 2;
                    *(uint32_t*)(g_vB + ((size_t)n * CH + o) * LL + mc) =
                        pk_bf16(vacc[set * 8 + j][0] + bo0, vacc[set * 8 + j][1] + bo0);
                    *(uint32_t*)(g_vB + ((size_t)n * CH + o + 8) * LL + mc) =
                        pk_bf16(vacc[set * 8 + j][2] + bo1, vacc[set * 8 + j][3] + bo1);
                }
            }
        }
    }
}

// ---------------------------------------------------------------------------
// Kernel B: stats (NO max — raw exp2 sums; scores bounded ~|15| so exp2 is
// always finite in fp32) + direct S[l][m] store. grid (32,4,2), 128 thr, (128,2).
// smem: kt 32K | qt db 2x16K
// ---------------------------------------------------------------------------
__global__ __launch_bounds__(128, 2) void stats_kernel()
{
    extern __shared__ char smc[];
    char* kt  = smc;
    char* qt0 = smc + 32768;
    char* qt1 = smc + 49152;
    uint32_t ktb = smem_u32(kt);
    uint32_t qtb[2] = {smem_u32(qt0), smem_u32(qt1)};

    int n = blockIdx.y, l0 = blockIdx.x * 128, t = threadIdx.x;
    int mh = blockIdx.z, mbase = mh * 2048;
    int lane = t & 31, w = t >> 5;
    int lw = w * 32;
    int gid = lane >> 2, tig = lane & 3;

    const uint4* ksrc = (const uint4*)(g_kT + ((size_t)n * LL + l0) * CH);
#pragma unroll
    for (int i = t; i < 2048; i += 128) {
        int row = i >> 4, ch = i & 15;
        *(uint4*)(kt + swz(row, ch, 256)) = ksrc[row * 16 + ch];
    }
    const uint4* qsrc = (const uint4*)(g_qT + (size_t)n * LL * CH);
#pragma unroll
    for (int i = t; i < 1024; i += 128) {
        int row = i >> 4, ch = i & 15;
        cpa16(qtb[0] + swz(row, ch, 256), &qsrc[(mbase + row) * 16 + ch]);
    }
    CPA_COMMIT();
    __syncthreads();

    uint32_t af[2][8][4];
#pragma unroll
    for (int lt = 0; lt < 2; lt++)
#pragma unroll
        for (int kk = 0; kk < 8; kk++)
            ldsm_x4(a_addr(ktb, lw + lt * 16, kk, lane, 256), af[lt][kk]);

    float rS[4];
#pragma unroll
    for (int i = 0; i < 4; i++) rS[i] = 0.f;

    for (int mc = 0; mc < 32; mc++) {
        __syncthreads();
        if (mc < 31) {
            int mb = mbase + (mc + 1) * 64;
#pragma unroll
            for (int i = t; i < 1024; i += 128) {
                int row = i >> 4, ch = i & 15;
                cpa16(qtb[(mc + 1) & 1] + swz(row, ch, 256), &qsrc[(mb + row) * 16 + ch]);
            }
        }
        CPA_COMMIT();
        CPA_WAIT(1);
        __syncthreads();

        uint32_t qb = qtb[mc & 1];
        float sacc[2][8][4];
#pragma unroll
        for (int lt = 0; lt < 2; lt++)
#pragma unroll
            for (int j = 0; j < 8; j++)
#pragma unroll
                for (int q = 0; q < 4; q++) sacc[lt][j][q] = 0.f;

#pragma unroll
        for (int kk = 0; kk < 8; kk++) {
#pragma unroll
            for (int jp = 0; jp < 4; jp++) {
                uint32_t b[4];
                ldsm_x4(b_addr(qb, jp * 16, kk, lane, 256), b);
                mma_bf16(sacc[0][jp * 2],     af[0][kk], b);
                mma_bf16(sacc[0][jp * 2 + 1], af[0][kk], b + 2);
                mma_bf16(sacc[1][jp * 2],     af[1][kk], b);
                mma_bf16(sacc[1][jp * 2 + 1], af[1][kk], b + 2);
            }
        }

        int mg0 = mbase + mc * 64;
#pragma unroll
        for (int lt = 0; lt < 2; lt++) {
            float s0 = 0.f, s1 = 0.f;
#pragma unroll
            for (int j = 0; j < 8; j++) {
                s0 += fexp2(sacc[lt][j][0]) + fexp2(sacc[lt][j][1]);
                s1 += fexp2(sacc[lt][j][2]) + fexp2(sacc[lt][j][3]);
            }
            rS[lt * 2]     += s0;
            rS[lt * 2 + 1] += s1;

            __nv_bfloat16* basep =
                g_s + ((size_t)(n * LL + l0 + lw + lt * 16 + gid)) * LL + mg0 + tig * 2;
#pragma unroll
            for (int j = 0; j < 8; j++) {
                *(uint32_t*)(basep + j * 8) =
                    pk_bf16(sacc[lt][j][0], sacc[lt][j][1]);
                *(uint32_t*)(basep + (size_t)8 * LL + j * 8) =
                    pk_bf16(sacc[lt][j][2], sacc[lt][j][3]);
            }
        }
    }

#pragma unroll
    for (int i = 0; i < 4; i++) {
#pragma unroll
        for (int d = 1; d < 4; d <<= 1)
            rS[i] += __shfl_xor_sync(0xffffffffu, rS[i], d);
    }
    if (tig == 0) {
        float* dst = mh ? g_mpB : g_mpA;
#pragma unroll
        for (int i = 0; i < 4; i++) {
            int r = n * LL + l0 + lw + (i >> 1) * 16 + gid + (i & 1) * 8;
            dst[r] = rS[i];      // raw sum of exp2
        }
    }
}

// ---------------------------------------------------------------------------
// Kernel B2: merge raw sums -> g_mp = log2(sumA + sumB)
// ---------------------------------------------------------------------------
__global__ __launch_bounds__(256) void merge_mp_kernel()
{
    int i = blockIdx.x * 256 + threadIdx.x;
    g_mp[i] = flog2(g_mpA[i] + g_mpB[i]);
}

// ---------------------------------------------------------------------------
// Kernel C: partial attn + folded combine. CTA m-tile 128, warp owns 32 m.
// S tiles [l 64][m 128]; B-fragments via ldmatrix.trans; exp on registers.
// After writing its partial, the SECOND CTA of each (m-tile, n) pair combines
// out = x + p0 + p1 (semaphore; reset for replays). grid (32,4,2), (128,2).
// smem: st db 2x16K | vt db 2x16K | mp db 2x256
// ---------------------------------------------------------------------------
__global__ __launch_bounds__(128, 2) void attn_kernel(
    const float* __restrict__ x, float* __restrict__ out)
{
    extern __shared__ char smc[];
    __shared__ int s_old;
    uint32_t base = smem_u32(smc);
    uint32_t stb[2] = {base, base + 16384};
    uint32_t vtb[2] = {base + 32768, base + 49152};
    float* mpf[2] = {(float*)(smc + 65536), (float*)(smc + 65792)};
    uint32_t mpb[2] = {base + 65536, base + 65792};

    int n = blockIdx.y, m0 = blockIdx.x * 128, t = threadIdx.x;
    int lh = blockIdx.z;
    int lbase = lh * 2048;
    int lane = t & 31, w = t >> 5;
    int mw = w * 32;
    int gid = lane >> 2, ecol = (lane & 3) * 2;

    const uint4* gs4  = (const uint4*)g_s;
    const uint4* vsrc = (const uint4*)(g_vB + (size_t)n * CH * LL);
    const float* mpg  = g_mp + n * LL;

    auto issue = [&](int i) {
        int buf = i & 1;
        int lcur = lbase + i * 64;
#pragma unroll
        for (int p = 0; p < 8; p++) {
            int idx = p * 128 + t;
            int row = idx >> 4, ch = idx & 15;
            cpa16(stb[buf] + swz(row, ch, 256),
                  &gs4[(((size_t)(n * LL + lcur + row)) * LL + m0) / 8 + ch]);
        }
#pragma unroll
        for (int p = 0; p < 8; p++) {
            int idx = p * 128 + t;
            int row = idx >> 3, ch = idx & 7;
            cpa16(vtb[buf] + swz(row, ch, 128), &vsrc[row * 512 + (lcur >> 3) + ch]);
        }
        if (t < 16) cpa16(mpb[buf] + t * 16, mpg + lcur + t * 4);
        CPA_COMMIT();
    };

    issue(0);

    float oacc[8][4][4];
#pragma unroll
    for (int i = 0; i < 8; i++)
#pragma unroll
        for (int j = 0; j < 4; j++)
#pragma unroll
            for (int q = 0; q < 4; q++) oacc[i][j][q] = 0.f;

    for (int lc = 0; lc < 32; lc++) {
        CPA_WAIT(0);
        __syncthreads();
        if (lc < 31) issue(lc + 1);

        int buf = lc & 1;
        const float* mp = mpf[buf];

#pragma unroll
        for (int s = 0; s < 4; s++) {
            uint32_t bb[8];
            ldsm_x4_trans(bt_addr(stb[buf], mw,      s, lane), bb);
            ldsm_x4_trans(bt_addr(stb[buf], mw + 16, s, lane), bb + 4);
            int l0s = s * 16 + ecol;
            float mpa = mp[l0s],     mpb_ = mp[l0s + 1];
            float mpc = mp[l0s + 8], mpd  = mp[l0s + 9];
#pragma unroll
            for (int r = 0; r < 8; r++) {
                float flo = __uint_as_float(bb[r] << 16);
                float fhi = __uint_as_float(bb[r] & 0xFFFF0000u);
                float s0 = (r & 1) ? mpc : mpa;
                float s1 = (r & 1) ? mpd : mpb_;
                bb[r] = pk_bf16(fexp2(flo - s0), fexp2(fhi - s1));
            }
#pragma unroll
            for (int ct = 0; ct < 8; ct++) {
                uint32_t a[4];
                ldsm_x4(a_addr(vtb[buf], ct * 16, s, lane, 128), a);
                mma_bf16(oacc[ct][0], a, bb);
                mma_bf16(oacc[ct][1], a, bb + 2);
                mma_bf16(oacc[ct][2], a, bb + 4);
                mma_bf16(oacc[ct][3], a, bb + 6);
            }
        }
    }

    // write partial
    float* pb = g_part + (size_t)lh * NB * CH * LL + (size_t)n * CH * LL;
#pragma unroll
    for (int ct = 0; ct < 8; ct++) {
        int c0 = ct * 16 + gid;
#pragma unroll
        for (int nt = 0; nt < 4; nt++) {
            int mcol = m0 + mw + nt * 8 + ecol;
            float* d = oacc[ct][nt];
            *(float2*)(pb + (size_t)c0 * LL + mcol)       = make_float2(d[0], d[1]);
            *(float2*)(pb + (size_t)(c0 + 8) * LL + mcol) = make_float2(d[2], d[3]);
        }
    }

    // folded combine: second arriver of (m-tile, n) does out = x + p0 + p1
    __threadfence();
    __syncthreads();
    if (t == 0) s_old = atomicAdd(&g_sem[n * 32 + blockIdx.x], 1);
    __syncthreads();
    if (s_old == 1) {
        __threadfence();
        const float* xb = x + (size_t)n * CH * LL;
        float* ob = out + (size_t)n * CH * LL;
        const float* p0 = g_part + (size_t)n * CH * LL;
        const float* p1 = g_part + (size_t)NB * CH * LL + (size_t)n * CH * LL;
#pragma unroll 4
        for (int i = t; i < 4096; i += 128) {
            int row = i >> 5, c4 = (i & 31) * 4;
            size_t off = (size_t)row * LL + m0 + c4;
            float4 a = *(const float4*)(xb + off);
            float4 b = *(const float4*)(p0 + off);
            float4 c = *(const float4*)(p1 + off);
            a.x += b.x + c.x; a.y += b.y + c.y;
            a.z += b.z + c.z; a.w += b.w + c.w;
            *(float4*)(ob + off) = a;
        }
        __syncthreads();
        if (t == 0) g_sem[n * 32 + blockIdx.x] = 0;   // replay-safe reset
    }
}

// ---------------------------------------------------------------------------
extern "C" void kernel_launch(void* const* d_in, const int* in_sizes, int n_in,
                              void* d_out, int out_size)
{
    const float* x  = (const float*)d_in[0];
    const float* Wq = (const float*)d_in[1];
    const float* bq = (const float*)d_in[2];
    const float* Wk = (const float*)d_in[3];
    const float* bk = (const float*)d_in[4];
    const float* Wv = (const float*)d_in[5];
    const float* bv = (const float*)d_in[6];
    float* out = (float*)d_out;

    cudaFuncSetAttribute(qkv_kernel,   cudaFuncAttributeMaxDynamicSharedMemorySize, 50176);
    cudaFuncSetAttribute(stats_kernel, cudaFuncAttributeMaxDynamicSharedMemorySize, 65536);
    cudaFuncSetAttribute(attn_kernel,  cudaFuncAttributeMaxDynamicSharedMemorySize, 66048);

    qkv_kernel<<<dim3(64, 4), 128, 50176>>>(x, Wq, bq, Wk, bk, Wv, bv);
    stats_kernel<<<dim3(32, 4, 2), 128, 65536>>>();
    merge_mp_kernel<<<(NB * LL) / 256, 256>>>();
    attn_kernel<<<dim3(32, 4, 2), 128, 66048>>>(x, out);
}

// round 16
// speedup vs baseline: 1.1004x; 1.1004x over previous
#include <cuda_runtime.h>
#include <cuda_bf16.h>
#include <stdint.h>

#define NB 4
#define CH 128
#define LL 4096
#define SCALE_L2E ((float)(0.08838834764831845 * 1.4426950408889634))

// ---------------------------------------------------------------------------
// Scratch (allocation-free: static device globals)
// ---------------------------------------------------------------------------
__device__ __nv_bfloat16  g_qT[(size_t)NB * LL * CH];  // q^T [n][m][c]
__device__ __nv_bfloat16  g_kT[(size_t)NB * LL * CH];  // k^T [n][l][c], pre-scaled by SCALE*log2e
__device__ __nv_bfloat16  g_vB[(size_t)NB * CH * LL];  // v   [n][c][l]
__device__ __nv_bfloat16  g_s[(size_t)NB * LL * LL];   // raw scores S [n][l][m] bf16 (134MB)
__device__ float          g_mpA[NB * LL];              // raw sum exp2 for m-half 0
__device__ float          g_mpB[NB * LL];              // raw sum exp2 for m-half 1
__device__ float          g_mp [NB * LL];              // merged log2(sum)
__device__ float          g_part[2 * (size_t)NB * CH * LL]; // attn partials per l-half

// ---------------------------------------------------------------------------
// Helpers
// ---------------------------------------------------------------------------
__device__ __forceinline__ uint32_t smem_u32(const void* p) {
    uint32_t a;
    asm("{ .reg .u64 t; cvta.to.shared.u64 t, %1; cvt.u32.u64 %0, t; }"
        : "=r"(a) : "l"(p));
    return a;
}
__device__ __forceinline__ uint32_t pk_bf16(float a, float b) {
    __nv_bfloat162 t = __floats2bfloat162_rn(a, b);
    return *reinterpret_cast<uint32_t*>(&t);
}
__device__ __forceinline__ float fexp2(float x) {
    float y; asm("ex2.approx.f32 %0, %1;" : "=f"(y) : "f"(x)); return y;
}
__device__ __forceinline__ float flog2(float x) {
    float y; asm("lg2.approx.f32 %0, %1;" : "=f"(y) : "f"(x)); return y;
}

__device__ __forceinline__ uint32_t swz(int row, int ch, int pitch) {
    return (uint32_t)row * (uint32_t)pitch + (uint32_t)((ch ^ (row & 7)) << 4);
}
__device__ __forceinline__ void ldsm_x4(uint32_t addr, uint32_t* r) {
    asm volatile("ldmatrix.sync.aligned.m8n8.x4.shared.b16 {%0,%1,%2,%3}, [%4];"
        : "=r"(r[0]), "=r"(r[1]), "=r"(r[2]), "=r"(r[3]) : "r"(addr));
}
__device__ __forceinline__ void ldsm_x4_trans(uint32_t addr, uint32_t* r) {
    asm volatile("ldmatrix.sync.aligned.m8n8.x4.trans.shared.b16 {%0,%1,%2,%3}, [%4];"
        : "=r"(r[0]), "=r"(r[1]), "=r"(r[2]), "=r"(r[3]) : "r"(addr));
}
__device__ __forceinline__ uint32_t a_addr(uint32_t tb, int r0, int kk, int lane, int pitch) {
    return tb + swz(r0 + (lane & 15), kk * 2 + (lane >> 4), pitch);
}
__device__ __forceinline__ uint32_t b_addr(uint32_t tb, int n0, int kk, int lane, int pitch) {
    int g = lane >> 3;
    return tb + swz(n0 + (lane & 7) + ((g & 2) ? 8 : 0), kk * 2 + (g & 1), pitch);
}
// trans B-fragment address: tile stored [l][m] pitch 256; n0 = m base, kk = 16-l block.
__device__ __forceinline__ uint32_t bt_addr(uint32_t tb, int n0, int kk, int lane) {
    int row  = kk * 16 + (lane & 7) + ((lane & 8) ? 8 : 0);
    int colm = n0 + ((lane & 16) ? 8 : 0);
    return tb + swz(row, colm >> 3, 256);
}
__device__ __forceinline__ void mma_bf16(float* d, const uint32_t* a, const uint32_t* b) {
    asm volatile(
        "mma.sync.aligned.m16n8k16.row.col.f32.bf16.bf16.f32 "
        "{%0,%1,%2,%3}, {%4,%5,%6,%7}, {%8,%9}, {%0,%1,%2,%3};"
        : "+f"(d[0]), "+f"(d[1]), "+f"(d[2]), "+f"(d[3])
        : "r"(a[0]), "r"(a[1]), "r"(a[2]), "r"(a[3]), "r"(b[0]), "r"(b[1]));
}
__device__ __forceinline__ void cpa16(uint32_t dst, const void* src) {
    asm volatile("cp.async.cg.shared.global [%0], [%1], 16;" :: "r"(dst), "l"(src));
}
#define CPA_COMMIT() asm volatile("cp.async.commit_group;" ::: "memory")
#define CPA_WAIT(n)  asm volatile("cp.async.wait_group %0;" :: "n"(n) : "memory")

// ---------------------------------------------------------------------------
// Kernel A: q/k/v via HMMA with in-kernel x transpose.
// grid (64,4), 128 thr. smem: xt 16K | ts/wt 33.3K (aliased) | bias 512
// ---------------------------------------------------------------------------
__global__ __launch_bounds__(128) void qkv_kernel(
    const float* __restrict__ x,
    const float* __restrict__ Wq, const float* __restrict__ bq,
    const float* __restrict__ Wk, const float* __restrict__ bk,
    const float* __restrict__ Wv, const float* __restrict__ bv)
{
    extern __shared__ char smc[];
    char*  xt   = smc;
    float* ts   = (float*)(smc + 16384);
    char*  wt   = smc + 16384;
    float* bias = (float*)(smc + 49664);
    uint32_t xtb = smem_u32(xt), wtb = smem_u32(wt);
    int n = blockIdx.y, m0 = blockIdx.x * 64, t = threadIdx.x;
    int lane = t & 31, w = t >> 5;

    const float* xb = x + ((size_t)n * CH + t) * LL + m0;
#pragma unroll
    for (int k = 0; k < 16; k++) {
        float4 f = *(const float4*)(xb + k * 4);
        ts[t * 65 + k * 4 + 0] = f.x;
        ts[t * 65 + k * 4 + 1] = f.y;
        ts[t * 65 + k * 4 + 2] = f.z;
        ts[t * 65 + k * 4 + 3] = f.w;
    }
    __syncthreads();

    {
        int ml = t >> 1, half = t & 1;
#pragma unroll
        for (int u = 0; u < 8; u++) {
            int cb = half * 64 + u * 8;
            uint4 o;
            o.x = pk_bf16(ts[(cb + 0) * 65 + ml], ts[(cb + 1) * 65 + ml]);
            o.y = pk_bf16(ts[(cb + 2) * 65 + ml], ts[(cb + 3) * 65 + ml]);
            o.z = pk_bf16(ts[(cb + 4) * 65 + ml], ts[(cb + 5) * 65 + ml]);
            o.w = pk_bf16(ts[(cb + 6) * 65 + ml], ts[(cb + 7) * 65 + ml]);
            *(uint4*)(xt + swz(ml, half * 8 + u, 256)) = o;
        }
    }

    const float* Wm[3] = {Wq, Wk, Wv};
    const float* Bv[3] = {bq, bk, bv};

    for (int wi = 0; wi < 3; wi++) {
        __syncthreads();
#pragma unroll
        for (int i = t; i < 2048; i += 128) {
            int row = i >> 4, ch = i & 15;
            const float* src = Wm[wi] + row * 128 + ch * 8;
            float4 f0 = *(const float4*)src;
            float4 f1 = *(const float4*)(src + 4);
            uint4 u;
            u.x = pk_bf16(f0.x, f0.y); u.y = pk_bf16(f0.z, f0.w);
            u.z = pk_bf16(f1.x, f1.y); u.w = pk_bf16(f1.z, f1.w);
            *(uint4*)(wt + swz(row, ch, 256)) = u;
        }
        bias[t] = Bv[wi][t];
        __syncthreads();

        if (wi < 2) {
            int lw = w * 16;
            float sacc[16][4];
#pragma unroll
            for (int j = 0; j < 16; j++)
#pragma unroll
                for (int q = 0; q < 4; q++) sacc[j][q] = 0.f;
#pragma unroll
            for (int kk = 0; kk < 8; kk++) {
                uint32_t a[4];
                ldsm_x4(a_addr(xtb, lw, kk, lane, 256), a);
#pragma unroll
                for (int jp = 0; jp < 8; jp++) {
                    uint32_t b[4];
                    ldsm_x4(b_addr(wtb, jp * 16, kk, lane, 256), b);
                    mma_bf16(sacc[jp * 2],     a, b);
                    mma_bf16(sacc[jp * 2 + 1], a, b + 2);
                }
            }
            int mrow = m0 + lw + (lane >> 2);
            __nv_bfloat16* dst = (wi == 0 ? g_qT : g_kT) + (size_t)n * LL * CH;
            float sc = (wi == 0) ? 1.0f : SCALE_L2E;
#pragma unroll
            for (int j = 0; j < 16; j++) {
                int o = (j >> 1) * 16 + (j & 1) * 8 + (lane & 3) * 2;
                float b0 = bias[o], b1 = bias[o + 1];
                *(uint32_t*)(dst + (size_t)mrow * CH + o) =
                    pk_bf16((sacc[j][0] + b0) * sc, (sacc[j][1] + b1) * sc);
                *(uint32_t*)(dst + (size_t)(mrow + 8) * CH + o) =
                    pk_bf16((sacc[j][2] + b0) * sc, (sacc[j][3] + b1) * sc);
            }
        } else {
            int rw2 = w * 32;
            float vacc[16][4];
#pragma unroll
            for (int j = 0; j < 16; j++)
#pragma unroll
                for (int q = 0; q < 4; q++) vacc[j][q] = 0.f;
#pragma unroll
            for (int kk = 0; kk < 8; kk++) {
                uint32_t a0[4], a1[4];
                ldsm_x4(a_addr(wtb, rw2,      kk, lane, 256), a0);
                ldsm_x4(a_addr(wtb, rw2 + 16, kk, lane, 256), a1);
#pragma unroll
                for (int bp = 0; bp < 4; bp++) {
                    uint32_t b[4];
                    ldsm_x4(b_addr(xtb, bp * 16, kk, lane, 256), b);
                    mma_bf16(vacc[bp * 2],         a0, b);
                    mma_bf16(vacc[bp * 2 + 1],     a0, b + 2);
                    mma_bf16(vacc[8 + bp * 2],     a1, b);
                    mma_bf16(vacc[8 + bp * 2 + 1], a1, b + 2);
                }
            }
#pragma unroll
            for (int set = 0; set < 2; set++) {
                int o = rw2 + set * 16 + (lane >> 2);
                float bo0 = bias[o], bo1 = bias[o + 8];
#pragma unroll
                for (int j = 0; j < 8; j++) {
                    int mc = m0 + j * 8 + (lane & 3) * 2;
                    *(uint32_t*)(g_vB + ((size_t)n * CH + o) * LL + mc) =
                        pk_bf16(vacc[set * 8 + j][0] + bo0, vacc[set * 8 + j][1] + bo0);
                    *(uint32_t*)(g_vB + ((size_t)n * CH + o + 8) * LL + mc) =
                        pk_bf16(vacc[set * 8 + j][2] + bo1, vacc[set * 8 + j][3] + bo1);
                }
            }
        }
    }
}

// ---------------------------------------------------------------------------
// Kernel B: stats (no-max: raw exp2 sums — scores bounded ~|15|, exp2 finite)
// + direct S[l][m] store. grid (32,4,2), 128 thr, (128,2).
// smem: kt 32K | qt db 2x16K
// ---------------------------------------------------------------------------
__global__ __launch_bounds__(128, 2) void stats_kernel()
{
    extern __shared__ char smc[];
    char* kt  = smc;
    char* qt0 = smc + 32768;
    char* qt1 = smc + 49152;
    uint32_t ktb = smem_u32(kt);
    uint32_t qtb[2] = {smem_u32(qt0), smem_u32(qt1)};

    int n = blockIdx.y, l0 = blockIdx.x * 128, t = threadIdx.x;
    int mh = blockIdx.z, mbase = mh * 2048;
    int lane = t & 31, w = t >> 5;
    int lw = w * 32;
    int gid = lane >> 2, tig = lane & 3;

    const uint4* ksrc = (const uint4*)(g_kT + ((size_t)n * LL + l0) * CH);
#pragma unroll
    for (int i = t; i < 2048; i += 128) {
        int row = i >> 4, ch = i & 15;
        *(uint4*)(kt + swz(row, ch, 256)) = ksrc[row * 16 + ch];
    }
    const uint4* qsrc = (const uint4*)(g_qT + (size_t)n * LL * CH);
#pragma unroll
    for (int i = t; i < 1024; i += 128) {
        int row = i >> 4, ch = i & 15;
        cpa16(qtb[0] + swz(row, ch, 256), &qsrc[(mbase + row) * 16 + ch]);
    }
    CPA_COMMIT();
    __syncthreads();

    uint32_t af[2][8][4];
#pragma unroll
    for (int lt = 0; lt < 2; lt++)
#pragma unroll
        for (int kk = 0; kk < 8; kk++)
            ldsm_x4(a_addr(ktb, lw + lt * 16, kk, lane, 256), af[lt][kk]);

    float rS[4];
#pragma unroll
    for (int i = 0; i < 4; i++) rS[i] = 0.f;

    for (int mc = 0; mc < 32; mc++) {
        __syncthreads();
        if (mc < 31) {
            int mb = mbase + (mc + 1) * 64;
#pragma unroll
            for (int i = t; i < 1024; i += 128) {
                int row = i >> 4, ch = i & 15;
                cpa16(qtb[(mc + 1) & 1] + swz(row, ch, 256), &qsrc[(mb + row) * 16 + ch]);
            }
        }
        CPA_COMMIT();
        CPA_WAIT(1);
        __syncthreads();

        uint32_t qb = qtb[mc & 1];
        float sacc[2][8][4];
#pragma unroll
        for (int lt = 0; lt < 2; lt++)
#pragma unroll
            for (int j = 0; j < 8; j++)
#pragma unroll
                for (int q = 0; q < 4; q++) sacc[lt][j][q] = 0.f;

#pragma unroll
        for (int kk = 0; kk < 8; kk++) {
#pragma unroll
            for (int jp = 0; jp < 4; jp++) {
                uint32_t b[4];
                ldsm_x4(b_addr(qb, jp * 16, kk, lane, 256), b);
                mma_bf16(sacc[0][jp * 2],     af[0][kk], b);
                mma_bf16(sacc[0][jp * 2 + 1], af[0][kk], b + 2);
                mma_bf16(sacc[1][jp * 2],     af[1][kk], b);
                mma_bf16(sacc[1][jp * 2 + 1], af[1][kk], b + 2);
            }
        }

        int mg0 = mbase + mc * 64;
#pragma unroll
        for (int lt = 0; lt < 2; lt++) {
            float s0 = 0.f, s1 = 0.f;
#pragma unroll
            for (int j = 0; j < 8; j++) {
                s0 += fexp2(sacc[lt][j][0]) + fexp2(sacc[lt][j][1]);
                s1 += fexp2(sacc[lt][j][2]) + fexp2(sacc[lt][j][3]);
            }
            rS[lt * 2]     += s0;
            rS[lt * 2 + 1] += s1;

            __nv_bfloat16* basep =
                g_s + ((size_t)(n * LL + l0 + lw + lt * 16 + gid)) * LL + mg0 + tig * 2;
#pragma unroll
            for (int j = 0; j < 8; j++) {
                *(uint32_t*)(basep + j * 8) =
                    pk_bf16(sacc[lt][j][0], sacc[lt][j][1]);
                *(uint32_t*)(basep + (size_t)8 * LL + j * 8) =
                    pk_bf16(sacc[lt][j][2], sacc[lt][j][3]);
            }
        }
    }

#pragma unroll
    for (int i = 0; i < 4; i++) {
#pragma unroll
        for (int d = 1; d < 4; d <<= 1)
            rS[i] += __shfl_xor_sync(0xffffffffu, rS[i], d);
    }
    if (tig == 0) {
        float* dst = mh ? g_mpB : g_mpA;
#pragma unroll
        for (int i = 0; i < 4; i++) {
            int r = n * LL + l0 + lw + (i >> 1) * 16 + gid + (i & 1) * 8;
            dst[r] = rS[i];
        }
    }
}

// ---------------------------------------------------------------------------
// Kernel B2: merge raw sums -> g_mp = log2(sumA + sumB)
// ---------------------------------------------------------------------------
__global__ __launch_bounds__(256) void merge_mp_kernel()
{
    int i = blockIdx.x * 256 + threadIdx.x;
    g_mp[i] = flog2(g_mpA[i] + g_mpB[i]);
}

// ---------------------------------------------------------------------------
// Kernel C: partial attn (R13-champion shape). CTA m-tile 128, warp owns 32 m.
// S tiles [l 64][m 128]; B-fragments via ldmatrix.trans; exp on registers.
// grid (32, 4, 2), 128 thr, launch_bounds(128,2).
// smem: st db 2x16K | vt db 2x16K | mp db 2x256
// ---------------------------------------------------------------------------
__global__ __launch_bounds__(128, 2) void attn_kernel()
{
    extern __shared__ char smc[];
    uint32_t base = smem_u32(smc);
    uint32_t stb[2] = {base, base + 16384};
    uint32_t vtb[2] = {base + 32768, base + 49152};
    float* mpf[2] = {(float*)(smc + 65536), (float*)(smc + 65792)};
    uint32_t mpb[2] = {base + 65536, base + 65792};

    int n = blockIdx.y, m0 = blockIdx.x * 128, t = threadIdx.x;
    int lh = blockIdx.z;
    int lbase = lh * 2048;
    int lane = t & 31, w = t >> 5;
    int mw = w * 32;
    int gid = lane >> 2, ecol = (lane & 3) * 2;

    const uint4* gs4  = (const uint4*)g_s;
    const uint4* vsrc = (const uint4*)(g_vB + (size_t)n * CH * LL);
    const float* mpg  = g_mp + n * LL;

    auto issue = [&](int i) {
        int buf = i & 1;
        int lcur = lbase + i * 64;
#pragma unroll
        for (int p = 0; p < 8; p++) {
            int idx = p * 128 + t;
            int row = idx >> 4, ch = idx & 15;
            cpa16(stb[buf] + swz(row, ch, 256),
                  &gs4[(((size_t)(n * LL + lcur + row)) * LL + m0) / 8 + ch]);
        }
#pragma unroll
        for (int p = 0; p < 8; p++) {
            int idx = p * 128 + t;
            int row = idx >> 3, ch = idx & 7;
            cpa16(vtb[buf] + swz(row, ch, 128), &vsrc[row * 512 + (lcur >> 3) + ch]);
        }
        if (t < 16) cpa16(mpb[buf] + t * 16, mpg + lcur + t * 4);
        CPA_COMMIT();
    };

    issue(0);

    float oacc[8][4][4];
#pragma unroll
    for (int i = 0; i < 8; i++)
#pragma unroll
        for (int j = 0; j < 4; j++)
#pragma unroll
            for (int q = 0; q < 4; q++) oacc[i][j][q] = 0.f;

    for (int lc = 0; lc < 32; lc++) {
        CPA_WAIT(0);
        __syncthreads();
        if (lc < 31) issue(lc + 1);

        int buf = lc & 1;
        const float* mp = mpf[buf];

#pragma unroll
        for (int s = 0; s < 4; s++) {
            uint32_t bb[8];
            ldsm_x4_trans(bt_addr(stb[buf], mw,      s, lane), bb);
            ldsm_x4_trans(bt_addr(stb[buf], mw + 16, s, lane), bb + 4);
            int l0s = s * 16 + ecol;
            float mpa = mp[l0s],     mpb_ = mp[l0s + 1];
            float mpc = mp[l0s + 8], mpd  = mp[l0s + 9];
#pragma unroll
            for (int r = 0; r < 8; r++) {
                float flo = __uint_as_float(bb[r] << 16);
                float fhi = __uint_as_float(bb[r] & 0xFFFF0000u);
                float s0 = (r & 1) ? mpc : mpa;
                float s1 = (r & 1) ? mpd : mpb_;
                bb[r] = pk_bf16(fexp2(flo - s0), fexp2(fhi - s1));
            }
#pragma unroll
            for (int ct = 0; ct < 8; ct++) {
                uint32_t a[4];
                ldsm_x4(a_addr(vtb[buf], ct * 16, s, lane, 128), a);
                mma_bf16(oacc[ct][0], a, bb);
                mma_bf16(oacc[ct][1], a, bb + 2);
                mma_bf16(oacc[ct][2], a, bb + 4);
                mma_bf16(oacc[ct][3], a, bb + 6);
            }
        }
    }

    float* pb = g_part + (size_t)lh * NB * CH * LL + (size_t)n * CH * LL;
#pragma unroll
    for (int ct = 0; ct < 8; ct++) {
        int c0 = ct * 16 + gid;
#pragma unroll
        for (int nt = 0; nt < 4; nt++) {
            int mcol = m0 + mw + nt * 8 + ecol;
            float* d = oacc[ct][nt];
            *(float2*)(pb + (size_t)c0 * LL + mcol)       = make_float2(d[0], d[1]);
            *(float2*)(pb + (size_t)(c0 + 8) * LL + mcol) = make_float2(d[2], d[3]);
        }
    }
}

// ---------------------------------------------------------------------------
// Kernel D: out = x + part0 + part1
// ---------------------------------------------------------------------------
__global__ __launch_bounds__(256) void combine_kernel(
    const float* __restrict__ x, float* __restrict__ out)
{
    size_t i = ((size_t)blockIdx.x * 256 + threadIdx.x) * 4;
    float4 a = *(const float4*)(x + i);
    float4 b = *(const float4*)(g_part + i);
    float4 c = *(const float4*)(g_part + (size_t)NB * CH * LL + i);
    a.x += b.x + c.x; a.y += b.y + c.y; a.z += b.z + c.z; a.w += b.w + c.w;
    *(float4*)(out + i) = a;
}

// ---------------------------------------------------------------------------
extern "C" void kernel_launch(void* const* d_in, const int* in_sizes, int n_in,
                              void* d_out, int out_size)
{
    const float* x  = (const float*)d_in[0];
    const float* Wq = (const float*)d_in[1];
    const float* bq = (const float*)d_in[2];
    const float* Wk = (const float*)d_in[3];
    const float* bk = (const float*)d_in[4];
    const float* Wv = (const float*)d_in[5];
    const float* bv = (const float*)d_in[6];
    float* out = (float*)d_out;

    cudaFuncSetAttribute(qkv_kernel,   cudaFuncAttributeMaxDynamicSharedMemorySize, 50176);
    cudaFuncSetAttribute(stats_kernel, cudaFuncAttributeMaxDynamicSharedMemorySize, 65536);
    cudaFuncSetAttribute(attn_kernel,  cudaFuncAttributeMaxDynamicSharedMemorySize, 66048);

    qkv_kernel<<<dim3(64, 4), 128, 50176>>>(x, Wq, bq, Wk, bk, Wv, bv);
    stats_kernel<<<dim3(32, 4, 2), 128, 65536>>>();
    merge_mp_kernel<<<(NB * LL) / 256, 256>>>();
    attn_kernel<<<dim3(32, 4, 2), 128, 66048>>>();
    combine_kernel<<<(NB * CH * LL) / 1024, 256>>>(x, out);
}

// round 17
// speedup vs baseline: 1.2119x; 1.1013x over previous
#include <cuda_runtime.h>
#include <cuda_bf16.h>
#include <stdint.h>

#define NB 4
#define CH 128
#define LL 4096
#define SCALE_L2E ((float)(0.08838834764831845 * 1.4426950408889634))

// ---------------------------------------------------------------------------
// Scratch (allocation-free: static device globals)
// ---------------------------------------------------------------------------
__device__ __nv_bfloat16  g_qT[(size_t)NB * LL * CH];  // q^T [n][m][c]
__device__ __nv_bfloat16  g_kT[(size_t)NB * LL * CH];  // k^T [n][l][c], pre-scaled by SCALE*log2e
__device__ __nv_bfloat16  g_vB[(size_t)NB * CH * LL];  // v   [n][c][l]
__device__ __nv_bfloat16  g_s[(size_t)NB * LL * LL];   // raw scores S [n][l][m] bf16 (134MB)
__device__ float          g_mpA[NB * LL];              // raw sum exp2 for m-half 0
__device__ float          g_mpB[NB * LL];              // raw sum exp2 for m-half 1
__device__ float          g_part[2 * (size_t)NB * CH * LL]; // attn partials per l-half

// ---------------------------------------------------------------------------
// Helpers
// ---------------------------------------------------------------------------
__device__ __forceinline__ uint32_t smem_u32(const void* p) {
    uint32_t a;
    asm("{ .reg .u64 t; cvta.to.shared.u64 t, %1; cvt.u32.u64 %0, t; }"
        : "=r"(a) : "l"(p));
    return a;
}
__device__ __forceinline__ uint32_t pk_bf16(float a, float b) {
    __nv_bfloat162 t = __floats2bfloat162_rn(a, b);
    return *reinterpret_cast<uint32_t*>(&t);
}
__device__ __forceinline__ float fexp2(float x) {
    float y; asm("ex2.approx.f32 %0, %1;" : "=f"(y) : "f"(x)); return y;
}
__device__ __forceinline__ float flog2(float x) {
    float y; asm("lg2.approx.f32 %0, %1;" : "=f"(y) : "f"(x)); return y;
}

__device__ __forceinline__ uint32_t swz(int row, int ch, int pitch) {
    return (uint32_t)row * (uint32_t)pitch + (uint32_t)((ch ^ (row & 7)) << 4);
}
__device__ __forceinline__ void ldsm_x4(uint32_t addr, uint32_t* r) {
    asm volatile("ldmatrix.sync.aligned.m8n8.x4.shared.b16 {%0,%1,%2,%3}, [%4];"
        : "=r"(r[0]), "=r"(r[1]), "=r"(r[2]), "=r"(r[3]) : "r"(addr));
}
__device__ __forceinline__ void ldsm_x4_trans(uint32_t addr, uint32_t* r) {
    asm volatile("ldmatrix.sync.aligned.m8n8.x4.trans.shared.b16 {%0,%1,%2,%3}, [%4];"
        : "=r"(r[0]), "=r"(r[1]), "=r"(r[2]), "=r"(r[3]) : "r"(addr));
}
__device__ __forceinline__ uint32_t a_addr(uint32_t tb, int r0, int kk, int lane, int pitch) {
    return tb + swz(r0 + (lane & 15), kk * 2 + (lane >> 4), pitch);
}
__device__ __forceinline__ uint32_t b_addr(uint32_t tb, int n0, int kk, int lane, int pitch) {
    int g = lane >> 3;
    return tb + swz(n0 + (lane & 7) + ((g & 2) ? 8 : 0), kk * 2 + (g & 1), pitch);
}
// trans B-fragment address: tile stored [l][m] pitch 256; n0 = m base, kk = 16-l block.
__device__ __forceinline__ uint32_t bt_addr(uint32_t tb, int n0, int kk, int lane) {
    int row  = kk * 16 + (lane & 7) + ((lane & 8) ? 8 : 0);
    int colm = n0 + ((lane & 16) ? 8 : 0);
    return tb + swz(row, colm >> 3, 256);
}
__device__ __forceinline__ void mma_bf16(float* d, const uint32_t* a, const uint32_t* b) {
    asm volatile(
        "mma.sync.aligned.m16n8k16.row.col.f32.bf16.bf16.f32 "
        "{%0,%1,%2,%3}, {%4,%5,%6,%7}, {%8,%9}, {%0,%1,%2,%3};"
        : "+f"(d[0]), "+f"(d[1]), "+f"(d[2]), "+f"(d[3])
        : "r"(a[0]), "r"(a[1]), "r"(a[2]), "r"(a[3]), "r"(b[0]), "r"(b[1]));
}
__device__ __forceinline__ void cpa16(uint32_t dst, const void* src) {
    asm volatile("cp.async.cg.shared.global [%0], [%1], 16;" :: "r"(dst), "l"(src));
}
#define CPA_COMMIT() asm volatile("cp.async.commit_group;" ::: "memory")
#define CPA_WAIT(n)  asm volatile("cp.async.wait_group %0;" :: "n"(n) : "memory")

// ---------------------------------------------------------------------------
// Kernel A: q/k/v via HMMA, one GEMM per CTA (z = which projection).
// grid (64, 4, 3), 128 thr. smem: xt 16K | ts/wt 33.3K (aliased) | bias 512
// ---------------------------------------------------------------------------
__global__ __launch_bounds__(128) void qkv_kernel(
    const float* __restrict__ x,
    const float* __restrict__ Wq, const float* __restrict__ bq,
    const float* __restrict__ Wk, const float* __restrict__ bk,
    const float* __restrict__ Wv, const float* __restrict__ bv)
{
    extern __shared__ char smc[];
    char*  xt   = smc;
    float* ts   = (float*)(smc + 16384);
    char*  wt   = smc + 16384;
    float* bias = (float*)(smc + 49664);
    uint32_t xtb = smem_u32(xt), wtb = smem_u32(wt);
    int n = blockIdx.y, m0 = blockIdx.x * 64, wi = blockIdx.z, t = threadIdx.x;
    int lane = t & 31, w = t >> 5;

    const float* Wm = (wi == 0) ? Wq : (wi == 1) ? Wk : Wv;
    const float* Bv = (wi == 0) ? bq : (wi == 1) ? bk : bv;

    // Phase 1: x fp32 tile -> ts (padded), coalesced
    const float* xb = x + ((size_t)n * CH + t) * LL + m0;
#pragma unroll
    for (int k = 0; k < 16; k++) {
        float4 f = *(const float4*)(xb + k * 4);
        ts[t * 65 + k * 4 + 0] = f.x;
        ts[t * 65 + k * 4 + 1] = f.y;
        ts[t * 65 + k * 4 + 2] = f.z;
        ts[t * 65 + k * 4 + 3] = f.w;
    }
    __syncthreads();

    // Phase 2: transpose+convert -> xt bf16 [m][c]
    {
        int ml = t >> 1, half = t & 1;
#pragma unroll
        for (int u = 0; u < 8; u++) {
            int cb = half * 64 + u * 8;
            uint4 o;
            o.x = pk_bf16(ts[(cb + 0) * 65 + ml], ts[(cb + 1) * 65 + ml]);
            o.y = pk_bf16(ts[(cb + 2) * 65 + ml], ts[(cb + 3) * 65 + ml]);
            o.z = pk_bf16(ts[(cb + 4) * 65 + ml], ts[(cb + 5) * 65 + ml]);
            o.w = pk_bf16(ts[(cb + 6) * 65 + ml], ts[(cb + 7) * 65 + ml]);
            *(uint4*)(xt + swz(ml, half * 8 + u, 256)) = o;
        }
    }
    __syncthreads();   // ts fully consumed before wt overwrites it

    // Phase 3: W bf16 tile (aliases ts)
#pragma unroll
    for (int i = t; i < 2048; i += 128) {
        int row = i >> 4, ch = i & 15;
        const float* src = Wm + row * 128 + ch * 8;
        float4 f0 = *(const float4*)src;
        float4 f1 = *(const float4*)(src + 4);
        uint4 u;
        u.x = pk_bf16(f0.x, f0.y); u.y = pk_bf16(f0.z, f0.w);
        u.z = pk_bf16(f1.x, f1.y); u.w = pk_bf16(f1.z, f1.w);
        *(uint4*)(wt + swz(row, ch, 256)) = u;
    }
    bias[t] = Bv[t];
    __syncthreads();

    if (wi < 2) {
        int lw = w * 16;
        float sacc[16][4];
#pragma unroll
        for (int j = 0; j < 16; j++)
#pragma unroll
            for (int q = 0; q < 4; q++) sacc[j][q] = 0.f;
#pragma unroll
        for (int kk = 0; kk < 8; kk++) {
            uint32_t a[4];
            ldsm_x4(a_addr(xtb, lw, kk, lane, 256), a);
#pragma unroll
            for (int jp = 0; jp < 8; jp++) {
                uint32_t b[4];
                ldsm_x4(b_addr(wtb, jp * 16, kk, lane, 256), b);
                mma_bf16(sacc[jp * 2],     a, b);
                mma_bf16(sacc[jp * 2 + 1], a, b + 2);
            }
        }
        int mrow = m0 + lw + (lane >> 2);
        __nv_bfloat16* dst = (wi == 0 ? g_qT : g_kT) + (size_t)n * LL * CH;
        float sc = (wi == 0) ? 1.0f : SCALE_L2E;
#pragma unroll
        for (int j = 0; j < 16; j++) {
            int o = (j >> 1) * 16 + (j & 1) * 8 + (lane & 3) * 2;
            float b0 = bias[o], b1 = bias[o + 1];
            *(uint32_t*)(dst + (size_t)mrow * CH + o) =
                pk_bf16((sacc[j][0] + b0) * sc, (sacc[j][1] + b1) * sc);
            *(uint32_t*)(dst + (size_t)(mrow + 8) * CH + o) =
                pk_bf16((sacc[j][2] + b0) * sc, (sacc[j][3] + b1) * sc);
        }
    } else {
        int rw2 = w * 32;
        float vacc[16][4];
#pragma unroll
        for (int j = 0; j < 16; j++)
#pragma unroll
            for (int q = 0; q < 4; q++) vacc[j][q] = 0.f;
#pragma unroll
        for (int kk = 0; kk < 8; kk++) {
            uint32_t a0[4], a1[4];
            ldsm_x4(a_addr(wtb, rw2,      kk, lane, 256), a0);
            ldsm_x4(a_addr(wtb, rw2 + 16, kk, lane, 256), a1);
#pragma unroll
            for (int bp = 0; bp < 4; bp++) {
                uint32_t b[4];
                ldsm_x4(b_addr(xtb, bp * 16, kk, lane, 256), b);
                mma_bf16(vacc[bp * 2],         a0, b);
                mma_bf16(vacc[bp * 2 + 1],     a0, b + 2);
                mma_bf16(vacc[8 + bp * 2],     a1, b);
                mma_bf16(vacc[8 + bp * 2 + 1], a1, b + 2);
            }
        }
#pragma unroll
        for (int set = 0; set < 2; set++) {
            int o = rw2 + set * 16 + (lane >> 2);
            float bo0 = bias[o], bo1 = bias[o + 8];
#pragma unroll
            for (int j = 0; j < 8; j++) {
                int mc = m0 + j * 8 + (lane & 3) * 2;
                *(uint32_t*)(g_vB + ((size_t)n * CH + o) * LL + mc) =
                    pk_bf16(vacc[set * 8 + j][0] + bo0, vacc[set * 8 + j][1] + bo0);
                *(uint32_t*)(g_vB + ((size_t)n * CH + o + 8) * LL + mc) =
                    pk_bf16(vacc[set * 8 + j][2] + bo1, vacc[set * 8 + j][3] + bo1);
            }
        }
    }
}

// ---------------------------------------------------------------------------
// Kernel B: stats (no-max raw exp2 sums) + direct S[l][m] store.
// grid (32,4,2), 128 thr, (128,2). smem: kt 32K | qt db 2x16K
// ---------------------------------------------------------------------------
__global__ __launch_bounds__(128, 2) void stats_kernel()
{
    extern __shared__ char smc[];
    char* kt  = smc;
    char* qt0 = smc + 32768;
    char* qt1 = smc + 49152;
    uint32_t ktb = smem_u32(kt);
    uint32_t qtb[2] = {smem_u32(qt0), smem_u32(qt1)};

    int n = blockIdx.y, l0 = blockIdx.x * 128, t = threadIdx.x;
    int mh = blockIdx.z, mbase = mh * 2048;
    int lane = t & 31, w = t >> 5;
    int lw = w * 32;
    int gid = lane >> 2, tig = lane & 3;

    const uint4* ksrc = (const uint4*)(g_kT + ((size_t)n * LL + l0) * CH);
#pragma unroll
    for (int i = t; i < 2048; i += 128) {
        int row = i >> 4, ch = i & 15;
        *(uint4*)(kt + swz(row, ch, 256)) = ksrc[row * 16 + ch];
    }
    const uint4* qsrc = (const uint4*)(g_qT + (size_t)n * LL * CH);
#pragma unroll
    for (int i = t; i < 1024; i += 128) {
        int row = i >> 4, ch = i & 15;
        cpa16(qtb[0] + swz(row, ch, 256), &qsrc[(mbase + row) * 16 + ch]);
    }
    CPA_COMMIT();
    __syncthreads();

    uint32_t af[2][8][4];
#pragma unroll
    for (int lt = 0; lt < 2; lt++)
#pragma unroll
        for (int kk = 0; kk < 8; kk++)
            ldsm_x4(a_addr(ktb, lw + lt * 16, kk, lane, 256), af[lt][kk]);

    float rS[4];
#pragma unroll
    for (int i = 0; i < 4; i++) rS[i] = 0.f;

    for (int mc = 0; mc < 32; mc++) {
        __syncthreads();
        if (mc < 31) {
            int mb = mbase + (mc + 1) * 64;
#pragma unroll
            for (int i = t; i < 1024; i += 128) {
                int row = i >> 4, ch = i & 15;
                cpa16(qtb[(mc + 1) & 1] + swz(row, ch, 256), &qsrc[(mb + row) * 16 + ch]);
            }
        }
        CPA_COMMIT();
        CPA_WAIT(1);
        __syncthreads();

        uint32_t qb = qtb[mc & 1];
        float sacc[2][8][4];
#pragma unroll
        for (int lt = 0; lt < 2; lt++)
#pragma unroll
            for (int j = 0; j < 8; j++)
#pragma unroll
                for (int q = 0; q < 4; q++) sacc[lt][j][q] = 0.f;

#pragma unroll
        for (int kk = 0; kk < 8; kk++) {
#pragma unroll
            for (int jp = 0; jp < 4; jp++) {
                uint32_t b[4];
                ldsm_x4(b_addr(qb, jp * 16, kk, lane, 256), b);
                mma_bf16(sacc[0][jp * 2],     af[0][kk], b);
                mma_bf16(sacc[0][jp * 2 + 1], af[0][kk], b + 2);
                mma_bf16(sacc[1][jp * 2],     af[1][kk], b);
                mma_bf16(sacc[1][jp * 2 + 1], af[1][kk], b + 2);
            }
        }

        int mg0 = mbase + mc * 64;
#pragma unroll
        for (int lt = 0; lt < 2; lt++) {
            float s0 = 0.f, s1 = 0.f;
#pragma unroll
            for (int j = 0; j < 8; j++) {
                s0 += fexp2(sacc[lt][j][0]) + fexp2(sacc[lt][j][1]);
                s1 += fexp2(sacc[lt][j][2]) + fexp2(sacc[lt][j][3]);
            }
            rS[lt * 2]     += s0;
            rS[lt * 2 + 1] += s1;

            __nv_bfloat16* basep =
                g_s + ((size_t)(n * LL + l0 + lw + lt * 16 + gid)) * LL + mg0 + tig * 2;
#pragma unroll
            for (int j = 0; j < 8; j++) {
                *(uint32_t*)(basep + j * 8) =
                    pk_bf16(sacc[lt][j][0], sacc[lt][j][1]);
                *(uint32_t*)(basep + (size_t)8 * LL + j * 8) =
                    pk_bf16(sacc[lt][j][2], sacc[lt][j][3]);
            }
        }
    }

#pragma unroll
    for (int i = 0; i < 4; i++) {
#pragma unroll
        for (int d = 1; d < 4; d <<= 1)
            rS[i] += __shfl_xor_sync(0xffffffffu, rS[i], d);
    }
    if (tig == 0) {
        float* dst = mh ? g_mpB : g_mpA;
#pragma unroll
        for (int i = 0; i < 4; i++) {
            int r = n * LL + l0 + lw + (i >> 1) * 16 + gid + (i & 1) * 8;
            dst[r] = rS[i];
        }
    }
}

// ---------------------------------------------------------------------------
// Kernel C: partial attn (R13 compute) + inline stats merge.
// mps[2048] = log2(g_mpA + g_mpB) computed once at start (8K smem),
// published by the iter-0 barrier; no merge kernel, no mp double-buffer.
// grid (32, 4, 2), 128 thr, (128,2). smem: st db 32K | vt db 32K | mps 8K
// ---------------------------------------------------------------------------
__global__ __launch_bounds__(128, 2) void attn_kernel()
{
    extern __shared__ char smc[];
    uint32_t base = smem_u32(smc);
    uint32_t stb[2] = {base, base + 16384};
    uint32_t vtb[2] = {base + 32768, base + 49152};
    float* mps = (float*)(smc + 65536);     // 2048 floats, this l-half

    int n = blockIdx.y, m0 = blockIdx.x * 128, t = threadIdx.x;
    int lh = blockIdx.z;
    int lbase = lh * 2048;
    int lane = t & 31, w = t >> 5;
    int mw = w * 32;
    int gid = lane >> 2, ecol = (lane & 3) * 2;

    const uint4* gs4  = (const uint4*)g_s;
    const uint4* vsrc = (const uint4*)(g_vB + (size_t)n * CH * LL);

    auto issue = [&](int i) {
        int buf = i & 1;
        int lcur = lbase + i * 64;
#pragma unroll
        for (int p = 0; p < 8; p++) {
            int idx = p * 128 + t;
            int row = idx >> 4, ch = idx & 15;
            cpa16(stb[buf] + swz(row, ch, 256),
                  &gs4[(((size_t)(n * LL + lcur + row)) * LL + m0) / 8 + ch]);
        }
#pragma unroll
        for (int p = 0; p < 8; p++) {
            int idx = p * 128 + t;
            int row = idx >> 3, ch = idx & 7;
            cpa16(vtb[buf] + swz(row, ch, 128), &vsrc[row * 512 + (lcur >> 3) + ch]);
        }
        CPA_COMMIT();
    };

    issue(0);

    // inline merge: mps = log2(sumA + sumB), overlapped with issue(0) flight;
    // published to all warps by the first CPA_WAIT+syncthreads below.
#pragma unroll
    for (int i = t; i < 2048; i += 128) {
        int gl = n * LL + lbase + i;
        mps[i] = flog2(g_mpA[gl] + g_mpB[gl]);
    }

    float oacc[8][4][4];
#pragma unroll
    for (int i = 0; i < 8; i++)
#pragma unroll
        for (int j = 0; j < 4; j++)
#pragma unroll
            for (int q = 0; q < 4; q++) oacc[i][j][q] = 0.f;

    for (int lc = 0; lc < 32; lc++) {
        CPA_WAIT(0);
        __syncthreads();
        if (lc < 31) issue(lc + 1);

        int buf = lc & 1;
        const float* mp = mps + lc * 64;

#pragma unroll
        for (int s = 0; s < 4; s++) {
            uint32_t bb[8];
            ldsm_x4_trans(bt_addr(stb[buf], mw,      s, lane), bb);
            ldsm_x4_trans(bt_addr(stb[buf], mw + 16, s, lane), bb + 4);
            int l0s = s * 16 + ecol;
            float mpa = mp[l0s],     mpb_ = mp[l0s + 1];
            float mpc = mp[l0s + 8], mpd  = mp[l0s + 9];
#pragma unroll
            for (int r = 0; r < 8; r++) {
                float flo = __uint_as_float(bb[r] << 16);
                float fhi = __uint_as_float(bb[r] & 0xFFFF0000u);
                float s0 = (r & 1) ? mpc : mpa;
                float s1 = (r & 1) ? mpd : mpb_;
                bb[r] = pk_bf16(fexp2(flo - s0), fexp2(fhi - s1));
            }
#pragma unroll
            for (int ct = 0; ct < 8; ct++) {
                uint32_t a[4];
                ldsm_x4(a_addr(vtb[buf], ct * 16, s, lane, 128), a);
                mma_bf16(oacc[ct][0], a, bb);
                mma_bf16(oacc[ct][1], a, bb + 2);
                mma_bf16(oacc[ct][2], a, bb + 4);
                mma_bf16(oacc[ct][3], a, bb + 6);
            }
        }
    }

    float* pb = g_part + (size_t)lh * NB * CH * LL + (size_t)n * CH * LL;
#pragma unroll
    for (int ct = 0; ct < 8; ct++) {
        int c0 = ct * 16 + gid;
#pragma unroll
        for (int nt = 0; nt < 4; nt++) {
            int mcol = m0 + mw + nt * 8 + ecol;
            float* d = oacc[ct][nt];
            *(float2*)(pb + (size_t)c0 * LL + mcol)       = make_float2(d[0], d[1]);
            *(float2*)(pb + (size_t)(c0 + 8) * LL + mcol) = make_float2(d[2], d[3]);
        }
    }
}

// ---------------------------------------------------------------------------
// Kernel D: out = x + part0 + part1
// ---------------------------------------------------------------------------
__global__ __launch_bounds__(256) void combine_kernel(
    const float* __restrict__ x, float* __restrict__ out)
{
    size_t i = ((size_t)blockIdx.x * 256 + threadIdx.x) * 4;
    float4 a = *(const float4*)(x + i);
    float4 b = *(const float4*)(g_part + i);
    float4 c = *(const float4*)(g_part + (size_t)NB * CH * LL + i);
    a.x += b.x + c.x; a.y += b.y + c.y; a.z += b.z + c.z; a.w += b.w + c.w;
    *(float4*)(out + i) = a;
}

// ---------------------------------------------------------------------------
extern "C" void kernel_launch(void* const* d_in, const int* in_sizes, int n_in,
                              void* d_out, int out_size)
{
    const float* x  = (const float*)d_in[0];
    const float* Wq = (const float*)d_in[1];
    const float* bq = (const float*)d_in[2];
    const float* Wk = (const float*)d_in[3];
    const float* bk = (const float*)d_in[4];
    const float* Wv = (const float*)d_in[5];
    const float* bv = (const float*)d_in[6];
    float* out = (float*)d_out;

    cudaFuncSetAttribute(qkv_kernel,   cudaFuncAttributeMaxDynamicSharedMemorySize, 50176);
    cudaFuncSetAttribute(stats_kernel, cudaFuncAttributeMaxDynamicSharedMemorySize, 65536);
    cudaFuncSetAttribute(attn_kernel,  cudaFuncAttributeMaxDynamicSharedMemorySize, 73728);

    qkv_kernel<<<dim3(64, 4, 3), 128, 50176>>>(x, Wq, bq, Wk, bk, Wv, bv);
    stats_kernel<<<dim3(32, 4, 2), 128, 65536>>>();
    attn_kernel<<<dim3(32, 4, 2), 128, 73728>>>();
    combine_kernel<<<(NB * CH * LL) / 1024, 256>>>(x, out);
}